// round 1
// baseline (speedup 1.0000x reference)
#include <cuda_runtime.h>
#include <cstdint>

// PadVariable: out[n,t,:] = x[n, src(n,t), :] masked by valid length.
//   rel = t - pad0[n]
//   src = rel<0 ? -rel : (rel<L ? rel : 2L-rel-2), clipped to [0, T-1]
//   valid = t < L + pad0[n] + pad1[n]
// x: (N, T, F) f32, out: (N, Tp, F) f32. N=64, T=4096, F=64 here, but N/T
// are derived from in_sizes and Tp from out_size so the kernel stays general
// for any F that is a multiple of 4.

__global__ void pad_variable_kernel(const float4* __restrict__ x4,
                                    const int* __restrict__ lens,
                                    const int* __restrict__ pad,  // (2, N)
                                    float4* __restrict__ out4,
                                    int N, int T, int Tp, int F4,
                                    long long total4) {
    long long i = (long long)blockIdx.x * blockDim.x + threadIdx.x;
    if (i >= total4) return;

    // i -> (n, t, f4). F4 is 16 for F=64 (power of two in this problem, but
    // handle generically with / and %; the compiler strength-reduces pow2).
    int f4 = (int)(i % F4);
    long long nt = i / F4;
    int t = (int)(nt % Tp);
    int n = (int)(nt / Tp);

    int L  = __ldg(&lens[n]);
    int p0 = __ldg(&pad[n]);
    int p1 = __ldg(&pad[N + n]);

    int rel = t - p0;
    int src = (rel < 0) ? -rel : ((rel < L) ? rel : (2 * L - rel - 2));
    src = min(max(src, 0), T - 1);

    float4 v;
    if (t < L + p0 + p1) {
        v = __ldg(&x4[((long long)n * T + src) * F4 + f4]);
    } else {
        v = make_float4(0.f, 0.f, 0.f, 0.f);
    }
    out4[i] = v;
}

extern "C" void kernel_launch(void* const* d_in, const int* in_sizes, int n_in,
                              void* d_out, int out_size) {
    const float* x    = (const float*)d_in[0];  // (N, T, F) float32
    const int*   lens = (const int*)d_in[1];    // (N,)
    const int*   pad  = (const int*)d_in[2];    // (2, N)
    // d_in[3] is Tp as a device scalar; we recover Tp on host from out_size.

    float* out = (float*)d_out;

    const int N = in_sizes[1];           // 64
    const int F = 64;                    // fixed feature dim for this problem
    const int T = in_sizes[0] / (N * F); // 4096
    const int Tp = out_size / (N * F);

    const int F4 = F / 4;
    long long total4 = (long long)N * Tp * F4;

    int threads = 256;
    long long blocks = (total4 + threads - 1) / threads;

    pad_variable_kernel<<<(unsigned)blocks, threads>>>(
        (const float4*)x, lens, pad, (float4*)out, N, T, Tp, F4, total4);
}

// round 2
// speedup vs baseline: 1.2358x; 1.2358x over previous
#include <cuda_runtime.h>
#include <cstdint>

// PadVariable reflect-pad gather, div-free 2D-grid version.
// out[n,t,:] = x[n, reflect(t - pad0[n], lens[n]), :], zero where t >= L+p0+p1.
// Layout: blockIdx.y = n, blockIdx.x = tile of TILE_T time steps.
// 256 threads: f4 = tid & (F4-1), trow = tid >> log2(F4). UNROLL=4 t's/thread.

#define F4_      16   // F=64 floats -> 16 float4
#define TROWS_   16   // 256 / F4_
#define UNROLL_  4
#define TILE_T_  (TROWS_ * UNROLL_)   // 64 t per block

__global__ __launch_bounds__(256)
void pad_variable_kernel(const float4* __restrict__ x4,
                         const int* __restrict__ lens,
                         const int* __restrict__ pad,  // (2, N)
                         float4* __restrict__ out4,
                         int N, int T, int Tp) {
    const int n    = blockIdx.y;
    const int tid  = threadIdx.x;
    const int f4   = tid & (F4_ - 1);
    const int trow = tid >> 4;
    const int t0   = blockIdx.x * TILE_T_ + trow;

    const int L  = __ldg(&lens[n]);
    const int p0 = __ldg(&pad[n]);
    const int p1 = __ldg(&pad[N + n]);
    const int vlim = L + p0 + p1;

    const float4* __restrict__ xrow = x4 + (long long)n * T * F4_;
    float4* __restrict__ orow       = out4 + (long long)n * Tp * F4_;

    int t[UNROLL_];
    int src[UNROLL_];
    bool inb[UNROLL_];
    bool val[UNROLL_];

    #pragma unroll
    for (int u = 0; u < UNROLL_; u++) {
        t[u] = t0 + u * TROWS_;
        inb[u] = t[u] < Tp;
        int rel = t[u] - p0;
        int s = (rel < 0) ? -rel : ((rel < L) ? rel : (2 * L - rel - 2));
        src[u] = min(max(s, 0), T - 1);
        val[u] = t[u] < vlim;
    }

    // Front-batched independent loads for MLP.
    float4 v[UNROLL_];
    #pragma unroll
    for (int u = 0; u < UNROLL_; u++) {
        if (inb[u] && val[u])
            v[u] = __ldg(&xrow[(long long)src[u] * F4_ + f4]);
        else
            v[u] = make_float4(0.f, 0.f, 0.f, 0.f);
    }

    #pragma unroll
    for (int u = 0; u < UNROLL_; u++) {
        if (inb[u])
            orow[(long long)t[u] * F4_ + f4] = v[u];
    }
}

extern "C" void kernel_launch(void* const* d_in, const int* in_sizes, int n_in,
                              void* d_out, int out_size) {
    const float* x    = (const float*)d_in[0];  // (N, T, F) float32
    const int*   lens = (const int*)d_in[1];    // (N,)
    const int*   pad  = (const int*)d_in[2];    // (2, N)

    float* out = (float*)d_out;

    const int N = in_sizes[1];           // 64
    const int F = 64;                    // feature dim (16 float4)
    const int T = in_sizes[0] / (N * F); // 4096
    const int Tp = out_size / (N * F);

    dim3 grid((Tp + TILE_T_ - 1) / TILE_T_, N);
    pad_variable_kernel<<<grid, 256>>>(
        (const float4*)x, lens, pad, (float4*)out, N, T, Tp);
}